// round 10
// baseline (speedup 1.0000x reference)
#include <cuda_runtime.h>
#include <cuda_fp16.h>

#define N_NODES 100000
#define E_MAX   3400000

// ---------------- scratch (device globals; no allocation allowed) ------------
__device__ int   g_cnt[N_NODES];
__device__ int   g_start[N_NODES];   // CSR segment start (order-free assignment)
__device__ float g_dinv[N_NODES];
__device__ int   g_total;
__device__ int   g_rank[E_MAX];      // edge's rank within its dst segment
__device__ int   g_csr[E_MAX];       // src indices grouped by dst
__device__ __align__(16) __half g_h1[(size_t)N_NODES * 128];  // fp16 features for gather
__device__ __align__(16) float  g_a1[(size_t)N_NODES * 128];  // fp32 layer-1 output
__device__ __align__(16) __half g_h2[(size_t)N_NODES * 64];
__device__ int   g_is64;

__device__ __forceinline__ unsigned to_tf32(float f) {
    unsigned r;
    asm("cvt.rna.tf32.f32 %0, %1;" : "=r"(r) : "f"(f));
    return r;
}

// ---------------- edge dtype detection (1 block) ------------------------------
__global__ void detect_kernel(const long long* __restrict__ edges) {
    __shared__ int bad;
    if (threadIdx.x == 0) bad = 0;
    __syncthreads();
    for (int k = threadIdx.x; k < 1024; k += blockDim.x) {
        long long v = edges[k];
        if (v < 0 || v >= N_NODES) bad = 1;   // benign race: all writers store 1
    }
    __syncthreads();
    if (threadIdx.x == 0) g_is64 = bad ? 0 : 1;
}

// count in-degree; the returned old value IS this edge's rank within its
// destination segment -> saved so fill needs no atomics at all.
__global__ void count_kernel(const void* __restrict__ edges, int E) {
    int e = blockIdx.x * blockDim.x + threadIdx.x;
    if (e >= E) return;
    int d;
    if (g_is64) d = (int)((const long long*)edges)[(size_t)E + e];
    else        d = ((const int*)edges)[E + e];
    g_rank[e] = atomicAdd(&g_cnt[d], 1);
}

// Per-block exclusive scan of degrees; one global atomic per block hands each
// node a disjoint CSR segment (segments need not be in node order). Also
// computes dinv.
__global__ void offset_kernel() {
    int i = blockIdx.x * blockDim.x + threadIdx.x;
    int c = (i < N_NODES) ? g_cnt[i] : 0;
    int lane = threadIdx.x & 31, wid = threadIdx.x >> 5;

    int v = c;
#pragma unroll
    for (int o = 1; o < 32; o <<= 1) {
        int t = __shfl_up_sync(0xFFFFFFFFu, v, o);
        if (lane >= o) v += t;
    }

    __shared__ int wsum[8], wbase[8];
    __shared__ int blockbase;
    if (lane == 31) wsum[wid] = v;
    __syncthreads();
    if (threadIdx.x == 0) {
        int run = 0;
#pragma unroll
        for (int w = 0; w < 8; w++) { wbase[w] = run; run += wsum[w]; }
        blockbase = atomicAdd(&g_total, run);
    }
    __syncthreads();

    if (i < N_NODES) {
        g_start[i] = blockbase + wbase[wid] + (v - c);
        g_dinv[i]  = rsqrtf((float)(c + 1));            // +1 = self loop
    }
}

// atomic-free fill: position comes from precomputed rank
__global__ void fill_kernel(const void* __restrict__ edges, int E) {
    int e = blockIdx.x * blockDim.x + threadIdx.x;
    if (e >= E) return;
    int s, d;
    if (g_is64) {
        const long long* p = (const long long*)edges;
        s = (int)p[e];
        d = (int)p[(size_t)E + e];
    } else {
        const int* p = (const int*)edges;
        s = p[e];
        d = p[E + e];
    }
    g_csr[g_start[d] + g_rank[e]] = s;
}

// ---------------- GEMM: Y[N, DOUT](fp16) = X[N,128](fp32) @ W[128, DOUT] ----
// tf32 mma.sync.m16n8k8. 256 threads / 8 warps; 64 rows per block.
template <int DOUT>
__global__ void gemm_mma_kernel(const float* __restrict__ X, const float* __restrict__ W,
                                __half* __restrict__ Y) {
    constexpr int XW = 128 + 4;      // padded X row (floats)
    constexpr int WW = DOUT + 4;     // padded W row
    extern __shared__ float smem[];
    float* sX = smem;                // 64 * XW
    float* sW = smem + 64 * XW;      // 128 * WW

    int tid = threadIdx.x, lane = tid & 31, wid = tid >> 5;
    int row0 = blockIdx.x * 64;

    for (int i = tid; i < 64 * 32; i += 256) {
        int r = i >> 5, c4 = (i & 31) * 4;
        int gr = row0 + r; if (gr >= N_NODES) gr = N_NODES - 1;
        float4 v = *(const float4*)&X[(size_t)gr * 128 + c4];
        float* dst = &sX[r * XW + c4];
        dst[0] = __uint_as_float(to_tf32(v.x));
        dst[1] = __uint_as_float(to_tf32(v.y));
        dst[2] = __uint_as_float(to_tf32(v.z));
        dst[3] = __uint_as_float(to_tf32(v.w));
    }
    for (int i = tid; i < 128 * (DOUT / 4); i += 256) {
        int r = i / (DOUT / 4), c4 = (i % (DOUT / 4)) * 4;
        float4 v = *(const float4*)&W[(size_t)r * DOUT + c4];
        float* dst = &sW[r * WW + c4];
        dst[0] = __uint_as_float(to_tf32(v.x));
        dst[1] = __uint_as_float(to_tf32(v.y));
        dst[2] = __uint_as_float(to_tf32(v.z));
        dst[3] = __uint_as_float(to_tf32(v.w));
    }
    __syncthreads();

    constexpr int NT = DOUT / 16;    // m16n8 tiles per warp
    int wr = (wid & 3) * 16;
    int wn = (wid >> 2) * (DOUT / 2);
    int g = lane >> 2, tig = lane & 3;

    float c[NT][4];
#pragma unroll
    for (int nt = 0; nt < NT; nt++)
#pragma unroll
        for (int j = 0; j < 4; j++) c[nt][j] = 0.0f;

#pragma unroll
    for (int ks = 0; ks < 16; ks++) {
        int k0 = ks * 8;
        unsigned a0 = __float_as_uint(sX[(wr + g)     * XW + k0 + tig]);
        unsigned a1 = __float_as_uint(sX[(wr + g + 8) * XW + k0 + tig]);
        unsigned a2 = __float_as_uint(sX[(wr + g)     * XW + k0 + tig + 4]);
        unsigned a3 = __float_as_uint(sX[(wr + g + 8) * XW + k0 + tig + 4]);
#pragma unroll
        for (int nt = 0; nt < NT; nt++) {
            unsigned b0 = __float_as_uint(sW[(k0 + tig)     * WW + wn + nt * 8 + g]);
            unsigned b1 = __float_as_uint(sW[(k0 + tig + 4) * WW + wn + nt * 8 + g]);
            asm("mma.sync.aligned.m16n8k8.row.col.f32.tf32.tf32.f32 "
                "{%0,%1,%2,%3}, {%4,%5,%6,%7}, {%8,%9}, {%0,%1,%2,%3};"
                : "+f"(c[nt][0]), "+f"(c[nt][1]), "+f"(c[nt][2]), "+f"(c[nt][3])
                : "r"(a0), "r"(a1), "r"(a2), "r"(a3), "r"(b0), "r"(b1));
        }
    }

    int r1 = row0 + wr + g;
    int r2 = r1 + 8;
#pragma unroll
    for (int nt = 0; nt < NT; nt++) {
        int col = wn + nt * 8 + tig * 2;
        __half2 p0 = __floats2half2_rn(c[nt][0], c[nt][1]);
        __half2 p1 = __floats2half2_rn(c[nt][2], c[nt][3]);
        if (r1 < N_NODES) *(unsigned*)&Y[(size_t)r1 * DOUT + col] = *(unsigned*)&p0;
        if (r2 < N_NODES) *(unsigned*)&Y[(size_t)r2 * DOUT + col] = *(unsigned*)&p1;
    }
}

// ---------------- aggregation: one warp per destination node ----------------
// out[n] = dinv[n]*sum_{s in N(n)} dinv[s]*H[s] + dinv[n]^2*H[n] + bias
template <int D, bool RELU>
__global__ void agg_kernel(const __half* __restrict__ H, const float* __restrict__ bias,
                           float* __restrict__ OUT) {
    int gw = (blockIdx.x * blockDim.x + threadIdx.x) >> 5;
    if (gw >= N_NODES) return;
    int lane = threadIdx.x & 31;
    constexpr int V = D / 32;        // halves per lane: 4 (D=128) or 2 (D=64)

    float acc[V];
#pragma unroll
    for (int c = 0; c < V; c++) acc[c] = 0.0f;

    int e = g_start[gw];
    const int e1 = e + g_cnt[gw];

    for (; e + 3 < e1; e += 4) {
        int s0 = __ldg(&g_csr[e]);
        int s1 = __ldg(&g_csr[e + 1]);
        int s2 = __ldg(&g_csr[e + 2]);
        int s3 = __ldg(&g_csr[e + 3]);
        float w0 = __ldg(&g_dinv[s0]);
        float w1 = __ldg(&g_dinv[s1]);
        float w2 = __ldg(&g_dinv[s2]);
        float w3 = __ldg(&g_dinv[s3]);
        if constexpr (V == 4) {
            uint2 a = *(const uint2*)&H[(size_t)s0 * D + lane * 4];
            uint2 b = *(const uint2*)&H[(size_t)s1 * D + lane * 4];
            uint2 c = *(const uint2*)&H[(size_t)s2 * D + lane * 4];
            uint2 d = *(const uint2*)&H[(size_t)s3 * D + lane * 4];
            float2 a0 = __half22float2(*(__half2*)&a.x), a1v = __half22float2(*(__half2*)&a.y);
            float2 b0 = __half22float2(*(__half2*)&b.x), b1v = __half22float2(*(__half2*)&b.y);
            float2 c0 = __half22float2(*(__half2*)&c.x), c1v = __half22float2(*(__half2*)&c.y);
            float2 d0 = __half22float2(*(__half2*)&d.x), d1v = __half22float2(*(__half2*)&d.y);
            acc[0] += w0 * a0.x + w1 * b0.x + w2 * c0.x + w3 * d0.x;
            acc[1] += w0 * a0.y + w1 * b0.y + w2 * c0.y + w3 * d0.y;
            acc[2] += w0 * a1v.x + w1 * b1v.x + w2 * c1v.x + w3 * d1v.x;
            acc[3] += w0 * a1v.y + w1 * b1v.y + w2 * c1v.y + w3 * d1v.y;
        } else {
            unsigned a = *(const unsigned*)&H[(size_t)s0 * D + lane * 2];
            unsigned b = *(const unsigned*)&H[(size_t)s1 * D + lane * 2];
            unsigned c = *(const unsigned*)&H[(size_t)s2 * D + lane * 2];
            unsigned d = *(const unsigned*)&H[(size_t)s3 * D + lane * 2];
            float2 a0 = __half22float2(*(__half2*)&a);
            float2 b0 = __half22float2(*(__half2*)&b);
            float2 c0 = __half22float2(*(__half2*)&c);
            float2 d0 = __half22float2(*(__half2*)&d);
            acc[0] += w0 * a0.x + w1 * b0.x + w2 * c0.x + w3 * d0.x;
            acc[1] += w0 * a0.y + w1 * b0.y + w2 * c0.y + w3 * d0.y;
        }
    }
    for (; e < e1; e++) {
        int s = __ldg(&g_csr[e]);
        float w = __ldg(&g_dinv[s]);
        if constexpr (V == 4) {
            uint2 a = *(const uint2*)&H[(size_t)s * D + lane * 4];
            float2 a0 = __half22float2(*(__half2*)&a.x), a1v = __half22float2(*(__half2*)&a.y);
            acc[0] += w * a0.x; acc[1] += w * a0.y;
            acc[2] += w * a1v.x; acc[3] += w * a1v.y;
        } else {
            unsigned a = *(const unsigned*)&H[(size_t)s * D + lane * 2];
            float2 a0 = __half22float2(*(__half2*)&a);
            acc[0] += w * a0.x; acc[1] += w * a0.y;
        }
    }

    float dd = g_dinv[gw];
    float dd2 = dd * dd;
    if constexpr (V == 4) {
        uint2 hsr = *(const uint2*)&H[(size_t)gw * D + lane * 4];
        float2 h0 = __half22float2(*(__half2*)&hsr.x);
        float2 h1v = __half22float2(*(__half2*)&hsr.y);
        float4 bv = *(const float4*)&bias[lane * 4];
        float o0 = dd * acc[0] + dd2 * h0.x + bv.x;
        float o1 = dd * acc[1] + dd2 * h0.y + bv.y;
        float o2 = dd * acc[2] + dd2 * h1v.x + bv.z;
        float o3 = dd * acc[3] + dd2 * h1v.y + bv.w;
        if constexpr (RELU) {
            o0 = fmaxf(o0, 0.0f); o1 = fmaxf(o1, 0.0f);
            o2 = fmaxf(o2, 0.0f); o3 = fmaxf(o3, 0.0f);
        }
        *(float4*)&OUT[(size_t)gw * D + lane * 4] = make_float4(o0, o1, o2, o3);
    } else {
        unsigned hsr = *(const unsigned*)&H[(size_t)gw * D + lane * 2];
        float2 h0 = __half22float2(*(__half2*)&hsr);
        float2 bv = *(const float2*)&bias[lane * 2];
        float o0 = dd * acc[0] + dd2 * h0.x + bv.x;
        float o1 = dd * acc[1] + dd2 * h0.y + bv.y;
        if constexpr (RELU) { o0 = fmaxf(o0, 0.0f); o1 = fmaxf(o1, 0.0f); }
        *(float2*)&OUT[(size_t)gw * D + lane * 2] = make_float2(o0, o1);
    }
}

// ---------------- launch -----------------------------------------------------
extern "C" void kernel_launch(void* const* d_in, const int* in_sizes, int n_in,
                              void* d_out, int out_size) {
    const float* x  = (const float*)d_in[0];
    const void*  ei = d_in[1];
    const float* W1 = (const float*)d_in[2];
    const float* b1 = (const float*)d_in[3];
    const float* W2 = (const float*)d_in[4];
    const float* b2 = (const float*)d_in[5];
    float* out = (float*)d_out;
    int E = in_sizes[1] / 2;

    const int SMEM1 = (64 * 132 + 128 * 132) * 4;   // ~99 KB
    const int SMEM2 = (64 * 132 + 128 * 68) * 4;    // ~67 KB
    cudaFuncSetAttribute(gemm_mma_kernel<128>, cudaFuncAttributeMaxDynamicSharedMemorySize, SMEM1);
    cudaFuncSetAttribute(gemm_mma_kernel<64>,  cudaFuncAttributeMaxDynamicSharedMemorySize, SMEM2);

    __half *h1, *h2;
    float *a1;
    int *cnt_p, *tot_p;
    cudaGetSymbolAddress((void**)&h1, g_h1);
    cudaGetSymbolAddress((void**)&a1, g_a1);
    cudaGetSymbolAddress((void**)&h2, g_h2);
    cudaGetSymbolAddress((void**)&cnt_p, g_cnt);
    cudaGetSymbolAddress((void**)&tot_p, g_total);

    const int TB = 256;
    int gE = (E + TB - 1) / TB;
    int gN = (N_NODES + TB - 1) / TB;
    int gG = (N_NODES + 63) / 64;

    // Serial single-stream schedule: overlapping bandwidth-heavy phases
    // thrashes L2 on this chip (measured +268us in R2). Keep phases ordered.
    cudaMemsetAsync(cnt_p, 0, N_NODES * sizeof(int), 0);
    cudaMemsetAsync(tot_p, 0, sizeof(int), 0);
    detect_kernel<<<1, 256>>>((const long long*)ei);
    count_kernel<<<gE, TB>>>(ei, E);          // also records per-edge rank
    offset_kernel<<<gN, TB>>>();              // block-scan + 391 atomics + dinv
    fill_kernel<<<gE, TB>>>(ei, E);           // atomic-free scatter

    gemm_mma_kernel<128><<<gG, 256, SMEM1>>>(x, W1, h1);
    agg_kernel<128, true><<<(N_NODES + 7) / 8, 256>>>(h1, b1, a1);
    gemm_mma_kernel<64><<<gG, 256, SMEM2>>>(a1, W2, h2);
    agg_kernel<64, false><<<(N_NODES + 7) / 8, 256>>>(h2, b2, out);
}

// round 11
// speedup vs baseline: 1.1473x; 1.1473x over previous
#include <cuda_runtime.h>
#include <cuda_fp16.h>

#define N_NODES 100000
#define E_MAX   3400000

// ---------------- scratch (device globals; no allocation allowed) ------------
__device__ int   g_cnt[N_NODES];
__device__ int   g_start[N_NODES];   // CSR segment start (order-free assignment)
__device__ float g_dinv[N_NODES];
__device__ int   g_total;
__device__ int   g_rank[E_MAX];      // edge's rank within its dst segment
__device__ int   g_csr[E_MAX];       // src indices grouped by dst
__device__ __align__(16) __half g_h1[(size_t)N_NODES * 128];  // dinv-premultiplied fp16
__device__ __align__(16) float  g_a1[(size_t)N_NODES * 128];  // fp32 layer-1 activation
__device__ __align__(16) __half g_h2[(size_t)N_NODES * 64];   // dinv-premultiplied fp16
__device__ int   g_is64;

__device__ __forceinline__ unsigned to_tf32(float f) {
    unsigned r;
    asm("cvt.rna.tf32.f32 %0, %1;" : "=r"(r) : "f"(f));
    return r;
}

// ---------------- edge dtype detection (1 block) + g_total zero ---------------
__global__ void detect_kernel(const long long* __restrict__ edges) {
    __shared__ int bad;
    if (threadIdx.x == 0) { bad = 0; g_total = 0; }
    __syncthreads();
    for (int k = threadIdx.x; k < 1024; k += blockDim.x) {
        long long v = edges[k];
        if (v < 0 || v >= N_NODES) bad = 1;   // benign race: all writers store 1
    }
    __syncthreads();
    if (threadIdx.x == 0) g_is64 = bad ? 0 : 1;
}

// count in-degree; returned old value IS this edge's rank within its segment.
__global__ void count_kernel(const void* __restrict__ edges, int E) {
    int e = blockIdx.x * blockDim.x + threadIdx.x;
    if (e >= E) return;
    int d;
    if (g_is64) d = (int)((const long long*)edges)[(size_t)E + e];
    else        d = ((const int*)edges)[E + e];
    g_rank[e] = atomicAdd(&g_cnt[d], 1);
}

// Per-block exclusive scan of degrees; one global atomic per block hands each
// node a disjoint CSR segment. Also computes dinv.
__global__ void offset_kernel() {
    int i = blockIdx.x * blockDim.x + threadIdx.x;
    int c = (i < N_NODES) ? g_cnt[i] : 0;
    int lane = threadIdx.x & 31, wid = threadIdx.x >> 5;

    int v = c;
#pragma unroll
    for (int o = 1; o < 32; o <<= 1) {
        int t = __shfl_up_sync(0xFFFFFFFFu, v, o);
        if (lane >= o) v += t;
    }

    __shared__ int wsum[8], wbase[8];
    __shared__ int blockbase;
    if (lane == 31) wsum[wid] = v;
    __syncthreads();
    if (threadIdx.x == 0) {
        int run = 0;
#pragma unroll
        for (int w = 0; w < 8; w++) { wbase[w] = run; run += wsum[w]; }
        blockbase = atomicAdd(&g_total, run);
    }
    __syncthreads();

    if (i < N_NODES) {
        g_start[i] = blockbase + wbase[wid] + (v - c);
        g_dinv[i]  = rsqrtf((float)(c + 1));            // +1 = self loop
    }
}

// atomic-free fill: position comes from precomputed rank
__global__ void fill_kernel(const void* __restrict__ edges, int E) {
    int e = blockIdx.x * blockDim.x + threadIdx.x;
    if (e >= E) return;
    int s, d;
    if (g_is64) {
        const long long* p = (const long long*)edges;
        s = (int)p[e];
        d = (int)p[(size_t)E + e];
    } else {
        const int* p = (const int*)edges;
        s = p[e];
        d = p[E + e];
    }
    g_csr[g_start[d] + g_rank[e]] = s;
}

// ---------------- GEMM: Y[N,DOUT](fp16) = dinv[row] * (X[N,128] @ W) --------
// tf32 mma.sync.m16n8k8; dinv premultiplied in the epilogue so aggregation
// needs NO per-edge dinv gather (out[n] = dinv[n]*(sum H' + H'[n]) + b).
template <int DOUT>
__global__ void gemm_mma_kernel(const float* __restrict__ X, const float* __restrict__ W,
                                __half* __restrict__ Y) {
    constexpr int XW = 128 + 4;      // padded X row (floats)
    constexpr int WW = DOUT + 4;     // padded W row
    extern __shared__ float smem[];
    float* sX = smem;                // 64 * XW
    float* sW = smem + 64 * XW;      // 128 * WW

    int tid = threadIdx.x, lane = tid & 31, wid = tid >> 5;
    int row0 = blockIdx.x * 64;

    for (int i = tid; i < 64 * 32; i += 256) {
        int r = i >> 5, c4 = (i & 31) * 4;
        int gr = row0 + r; if (gr >= N_NODES) gr = N_NODES - 1;
        float4 v = *(const float4*)&X[(size_t)gr * 128 + c4];
        float* dst = &sX[r * XW + c4];
        dst[0] = __uint_as_float(to_tf32(v.x));
        dst[1] = __uint_as_float(to_tf32(v.y));
        dst[2] = __uint_as_float(to_tf32(v.z));
        dst[3] = __uint_as_float(to_tf32(v.w));
    }
    for (int i = tid; i < 128 * (DOUT / 4); i += 256) {
        int r = i / (DOUT / 4), c4 = (i % (DOUT / 4)) * 4;
        float4 v = *(const float4*)&W[(size_t)r * DOUT + c4];
        float* dst = &sW[r * WW + c4];
        dst[0] = __uint_as_float(to_tf32(v.x));
        dst[1] = __uint_as_float(to_tf32(v.y));
        dst[2] = __uint_as_float(to_tf32(v.z));
        dst[3] = __uint_as_float(to_tf32(v.w));
    }
    __syncthreads();

    constexpr int NT = DOUT / 16;    // m16n8 tiles per warp
    int wr = (wid & 3) * 16;
    int wn = (wid >> 2) * (DOUT / 2);
    int g = lane >> 2, tig = lane & 3;

    float c[NT][4];
#pragma unroll
    for (int nt = 0; nt < NT; nt++)
#pragma unroll
        for (int j = 0; j < 4; j++) c[nt][j] = 0.0f;

#pragma unroll
    for (int ks = 0; ks < 16; ks++) {
        int k0 = ks * 8;
        unsigned a0 = __float_as_uint(sX[(wr + g)     * XW + k0 + tig]);
        unsigned a1 = __float_as_uint(sX[(wr + g + 8) * XW + k0 + tig]);
        unsigned a2 = __float_as_uint(sX[(wr + g)     * XW + k0 + tig + 4]);
        unsigned a3 = __float_as_uint(sX[(wr + g + 8) * XW + k0 + tig + 4]);
#pragma unroll
        for (int nt = 0; nt < NT; nt++) {
            unsigned b0 = __float_as_uint(sW[(k0 + tig)     * WW + wn + nt * 8 + g]);
            unsigned b1 = __float_as_uint(sW[(k0 + tig + 4) * WW + wn + nt * 8 + g]);
            asm("mma.sync.aligned.m16n8k8.row.col.f32.tf32.tf32.f32 "
                "{%0,%1,%2,%3}, {%4,%5,%6,%7}, {%8,%9}, {%0,%1,%2,%3};"
                : "+f"(c[nt][0]), "+f"(c[nt][1]), "+f"(c[nt][2]), "+f"(c[nt][3])
                : "r"(a0), "r"(a1), "r"(a2), "r"(a3), "r"(b0), "r"(b1));
        }
    }

    int r1 = row0 + wr + g;
    int r2 = r1 + 8;
    float d1 = (r1 < N_NODES) ? g_dinv[r1] : 0.0f;
    float d2 = (r2 < N_NODES) ? g_dinv[r2] : 0.0f;
#pragma unroll
    for (int nt = 0; nt < NT; nt++) {
        int col = wn + nt * 8 + tig * 2;
        __half2 p0 = __floats2half2_rn(c[nt][0] * d1, c[nt][1] * d1);
        __half2 p1 = __floats2half2_rn(c[nt][2] * d2, c[nt][3] * d2);
        if (r1 < N_NODES) *(unsigned*)&Y[(size_t)r1 * DOUT + col] = *(unsigned*)&p0;
        if (r2 < N_NODES) *(unsigned*)&Y[(size_t)r2 * DOUT + col] = *(unsigned*)&p1;
    }
}

// ---------------- aggregation: one warp per destination node ----------------
// H' is dinv-premultiplied: out[n] = dinv[n]*(sum_{s} H'[s] + H'[n]) + bias.
// Pure gather+sum: single dependent load level (csr -> H'), no dinv stream.
template <int D, bool RELU>
__global__ void agg_kernel(const __half* __restrict__ H, const float* __restrict__ bias,
                           float* __restrict__ OUT) {
    int gw = (blockIdx.x * blockDim.x + threadIdx.x) >> 5;
    if (gw >= N_NODES) return;
    int lane = threadIdx.x & 31;
    constexpr int V = D / 32;        // halves per lane: 4 (D=128) or 2 (D=64)

    float acc[V];
    // seed with own premultiplied row (self-loop term)
    if constexpr (V == 4) {
        uint2 hs = *(const uint2*)&H[(size_t)gw * D + lane * 4];
        float2 h0 = __half22float2(*(__half2*)&hs.x);
        float2 h1 = __half22float2(*(__half2*)&hs.y);
        acc[0] = h0.x; acc[1] = h0.y; acc[2] = h1.x; acc[3] = h1.y;
    } else {
        unsigned hs = *(const unsigned*)&H[(size_t)gw * D + lane * 2];
        float2 h0 = __half22float2(*(__half2*)&hs);
        acc[0] = h0.x; acc[1] = h0.y;
    }

    int e = g_start[gw];
    const int e1 = e + g_cnt[gw];

    for (; e + 3 < e1; e += 4) {
        int s0 = __ldg(&g_csr[e]);
        int s1 = __ldg(&g_csr[e + 1]);
        int s2 = __ldg(&g_csr[e + 2]);
        int s3 = __ldg(&g_csr[e + 3]);
        if constexpr (V == 4) {
            uint2 a = *(const uint2*)&H[(size_t)s0 * D + lane * 4];
            uint2 b = *(const uint2*)&H[(size_t)s1 * D + lane * 4];
            uint2 c = *(const uint2*)&H[(size_t)s2 * D + lane * 4];
            uint2 d = *(const uint2*)&H[(size_t)s3 * D + lane * 4];
            float2 a0 = __half22float2(*(__half2*)&a.x), a1v = __half22float2(*(__half2*)&a.y);
            float2 b0 = __half22float2(*(__half2*)&b.x), b1v = __half22float2(*(__half2*)&b.y);
            float2 c0 = __half22float2(*(__half2*)&c.x), c1v = __half22float2(*(__half2*)&c.y);
            float2 d0 = __half22float2(*(__half2*)&d.x), d1v = __half22float2(*(__half2*)&d.y);
            acc[0] += (a0.x + b0.x) + (c0.x + d0.x);
            acc[1] += (a0.y + b0.y) + (c0.y + d0.y);
            acc[2] += (a1v.x + b1v.x) + (c1v.x + d1v.x);
            acc[3] += (a1v.y + b1v.y) + (c1v.y + d1v.y);
        } else {
            unsigned a = *(const unsigned*)&H[(size_t)s0 * D + lane * 2];
            unsigned b = *(const unsigned*)&H[(size_t)s1 * D + lane * 2];
            unsigned c = *(const unsigned*)&H[(size_t)s2 * D + lane * 2];
            unsigned d = *(const unsigned*)&H[(size_t)s3 * D + lane * 2];
            float2 a0 = __half22float2(*(__half2*)&a);
            float2 b0 = __half22float2(*(__half2*)&b);
            float2 c0 = __half22float2(*(__half2*)&c);
            float2 d0 = __half22float2(*(__half2*)&d);
            acc[0] += (a0.x + b0.x) + (c0.x + d0.x);
            acc[1] += (a0.y + b0.y) + (c0.y + d0.y);
        }
    }
    for (; e < e1; e++) {
        int s = __ldg(&g_csr[e]);
        if constexpr (V == 4) {
            uint2 a = *(const uint2*)&H[(size_t)s * D + lane * 4];
            float2 a0 = __half22float2(*(__half2*)&a.x), a1v = __half22float2(*(__half2*)&a.y);
            acc[0] += a0.x; acc[1] += a0.y; acc[2] += a1v.x; acc[3] += a1v.y;
        } else {
            unsigned a = *(const unsigned*)&H[(size_t)s * D + lane * 2];
            float2 a0 = __half22float2(*(__half2*)&a);
            acc[0] += a0.x; acc[1] += a0.y;
        }
    }

    float dd = g_dinv[gw];
    if constexpr (V == 4) {
        float4 bv = *(const float4*)&bias[lane * 4];
        float o0 = dd * acc[0] + bv.x;
        float o1 = dd * acc[1] + bv.y;
        float o2 = dd * acc[2] + bv.z;
        float o3 = dd * acc[3] + bv.w;
        if constexpr (RELU) {
            o0 = fmaxf(o0, 0.0f); o1 = fmaxf(o1, 0.0f);
            o2 = fmaxf(o2, 0.0f); o3 = fmaxf(o3, 0.0f);
        }
        *(float4*)&OUT[(size_t)gw * D + lane * 4] = make_float4(o0, o1, o2, o3);
    } else {
        float2 bv = *(const float2*)&bias[lane * 2];
        float o0 = dd * acc[0] + bv.x;
        float o1 = dd * acc[1] + bv.y;
        if constexpr (RELU) { o0 = fmaxf(o0, 0.0f); o1 = fmaxf(o1, 0.0f); }
        *(float2*)&OUT[(size_t)gw * D + lane * 2] = make_float2(o0, o1);
    }
}

// ---------------- launch -----------------------------------------------------
extern "C" void kernel_launch(void* const* d_in, const int* in_sizes, int n_in,
                              void* d_out, int out_size) {
    const float* x  = (const float*)d_in[0];
    const void*  ei = d_in[1];
    const float* W1 = (const float*)d_in[2];
    const float* b1 = (const float*)d_in[3];
    const float* W2 = (const float*)d_in[4];
    const float* b2 = (const float*)d_in[5];
    float* out = (float*)d_out;
    int E = in_sizes[1] / 2;

    const int SMEM1 = (64 * 132 + 128 * 132) * 4;   // ~99 KB
    const int SMEM2 = (64 * 132 + 128 * 68) * 4;    // ~67 KB
    cudaFuncSetAttribute(gemm_mma_kernel<128>, cudaFuncAttributeMaxDynamicSharedMemorySize, SMEM1);
    cudaFuncSetAttribute(gemm_mma_kernel<64>,  cudaFuncAttributeMaxDynamicSharedMemorySize, SMEM2);

    __half *h1, *h2;
    float *a1;
    int *cnt_p;
    cudaGetSymbolAddress((void**)&h1, g_h1);
    cudaGetSymbolAddress((void**)&a1, g_a1);
    cudaGetSymbolAddress((void**)&h2, g_h2);
    cudaGetSymbolAddress((void**)&cnt_p, g_cnt);

    const int TB = 256;
    int gE = (E + TB - 1) / TB;
    int gN = (N_NODES + TB - 1) / TB;
    int gG = (N_NODES + 63) / 64;

    // Serial single-stream schedule: overlapping bandwidth-heavy phases
    // thrashes L2 on this chip (measured +268us in R2). Keep phases ordered.
    cudaMemsetAsync(cnt_p, 0, N_NODES * sizeof(int), 0);
    detect_kernel<<<1, 256>>>((const long long*)ei);  // also zeroes g_total
    count_kernel<<<gE, TB>>>(ei, E);          // also records per-edge rank
    offset_kernel<<<gN, TB>>>();              // block-scan + 391 atomics + dinv
    fill_kernel<<<gE, TB>>>(ei, E);           // atomic-free scatter

    gemm_mma_kernel<128><<<gG, 256, SMEM1>>>(x, W1, h1);
    agg_kernel<128, true><<<(N_NODES + 7) / 8, 256>>>(h1, b1, a1);
    gemm_mma_kernel<64><<<gG, 256, SMEM2>>>(a1, W2, h2);
    agg_kernel<64, false><<<(N_NODES + 7) / 8, 256>>>(h2, b2, out);
}